// round 11
// baseline (speedup 1.0000x reference)
#include <cuda_runtime.h>
#include <cuda_fp16.h>
#include <cstdint>

#define N_ENT   100000
#define N_DRUG  2000
#define N_REL   51
#define N_EDGE  1000000
#define DIM     64
#define BUCKET  64          // per-head capacity; Poisson(10) max over 100K ~35

// fp16 tables (row = 64 halves = 128B = one cache line).
// Rel tables have a leading ZERO row (row 0 never written): pad edge slots
// are packed-0 -> gather ent[0] (valid row) * rel[0] (zeros) -> contribute 0.
__device__ __half2  g_ent0h[N_ENT * 32];
__device__ __half2  g_entA [N_ENT * 32];
__device__ __half2  g_entB [N_ENT * 32];
__device__ __half2  g_rel0z[(N_REL + 1) * 32];   // fp16 rel0, shifted +1
__device__ __half2  g_relnz[(N_REL + 1) * 32];   // fp16 norm(rel0), shifted +1
__device__ int      g_cnt  [N_ENT];
__device__ unsigned g_edges[N_ENT * BUCKET];     // packed: tail | (rel+1)<<17

static __device__ __forceinline__ __half2 u2h(unsigned u) {
    return *reinterpret_cast<__half2*>(&u);
}
static __device__ __forceinline__ unsigned h2u(__half2 h) {
    return *reinterpret_cast<unsigned*>(&h);
}

// ---------------------------------------------------------------------------
// Convert ent0 (fp32) -> fp16 table
// ---------------------------------------------------------------------------
__global__ void conv_kernel(const float2* __restrict__ ent0) {
    int i = blockIdx.x * blockDim.x + threadIdx.x;
    if (i < N_ENT * 32)
        g_ent0h[i] = __float22half2_rn(ent0[i]);
}

// ---------------------------------------------------------------------------
// Bucket fill: 8 edges per thread (8 independent ATOMG.ADDs in flight)
// ---------------------------------------------------------------------------
__global__ void fill_kernel(const int* __restrict__ eidx,
                            const int* __restrict__ etype) {
    int base = (blockIdx.x * blockDim.x + threadIdx.x) * 8;
    #pragma unroll
    for (int k = 0; k < 8; k++) {
        int e = base + k;
        if (e < N_EDGE) {
            int h  = eidx[e];
            int tl = eidx[N_EDGE + e];
            int r  = etype[e];
            int pos = atomicAdd(&g_cnt[h], 1);
            if (pos < BUCKET)
                g_edges[(long long)h * BUCKET + pos] =
                    (unsigned)tl | ((unsigned)(r + 1) << 17);
        }
    }
}

// ---------------------------------------------------------------------------
// Relations (once): out_rel = rel0 + 3*normalize(rel0) (norm is idempotent);
// fp16 shifted tables rows 1..N_REL (row 0 stays all-zero).
// ---------------------------------------------------------------------------
__global__ void rel_kernel(const float* __restrict__ rel0,
                           float* __restrict__ out_rel) {
    int row  = blockIdx.x;
    int lane = threadIdx.x;

    float2 v = reinterpret_cast<const float2*>(rel0)[row * 32 + lane];
    float ss = v.x * v.x + v.y * v.y;
    #pragma unroll
    for (int o = 16; o > 0; o >>= 1)
        ss += __shfl_xor_sync(0xFFFFFFFFu, ss, o);

    float inv = 1.0f / fmaxf(sqrtf(ss), 1e-12f);
    float2 n = { v.x * inv, v.y * inv };

    g_rel0z[(row + 1) * 32 + lane] = __float22half2_rn(v);
    g_relnz[(row + 1) * 32 + lane] = __float22half2_rn(n);

    float2 o2 = { v.x + 3.0f * n.x, v.y + 3.0f * n.y };
    reinterpret_cast<float2*>(out_rel)[row * 32 + lane] = o2;
}

// ---------------------------------------------------------------------------
// Fused gather + L2-normalize, fp16 tables. One warp per row; HALF-WARP PER
// EDGE: lanes 0-15 (sub=0) process edge i, lanes 16-31 (sub=1) edge i+1.
// Each lane loads uint2 (= 4 halves = dims 4q..4q+3) via LDG.64; one shfl
// serves two edges. Chunk = 8 edges (4 per half), fp16 chain depth <= 4,
// per-chunk flush to fp32. Pad slots hit the rel zero-row -> contribute 0.
//   final_hop=0: dst[row] = fp16(n)
//   final_hop=1: out_ent = base + entA + entB + n ; ditto drug rows
// ---------------------------------------------------------------------------
__global__ void __launch_bounds__(256)
gather_kernel(const __half2* __restrict__ ent,
              const __half2* __restrict__ rel,
              __half2*       __restrict__ dst,
              const float4*  __restrict__ base_ent,
              const float4*  __restrict__ base_drug,
              float4*        __restrict__ out_ent,
              float4*        __restrict__ out_drug,
              int final_hop) {
    int row  = (blockIdx.x * blockDim.x + threadIdx.x) >> 5;
    int lane = threadIdx.x & 31;
    if (row >= N_ENT) return;

    int sub = lane >> 4;      // which edge of each pair this half-warp owns
    int q   = lane & 15;      // uint2 (16B? no: 8B) index within the row

    int deg = g_cnt[row];
    if (deg > BUCKET) deg = BUCKET;
    long long ebase = (long long)row * BUCKET;
    unsigned myp = g_edges[ebase + lane];   // coalesced: row's first 32 edges

    const uint2* entq = reinterpret_cast<const uint2*>(ent) + q;
    const uint2* relq = reinterpret_cast<const uint2*>(rel) + q;

    float f0 = 0.f, f1 = 0.f, f2 = 0.f, f3 = 0.f;
    int dmain  = deg < 32 ? deg : 32;
    int chunks = (dmain + 7) >> 3;          // 8 edges per chunk (4 per half)
    if (chunks == 0) chunks = 1;            // deg==0: one all-pad chunk

    for (int c = 0; c < chunks; c++) {
        __half2 accP = __float2half2_rn(0.f);
        __half2 accQ = __float2half2_rn(0.f);
        #pragma unroll
        for (int s = 0; s < 4; s++) {
            unsigned p = __shfl_sync(0xFFFFFFFFu, myp, c * 8 + s * 2 + sub);
            uint2 a = entq[(p & 0x1FFFFu) * 16];
            uint2 b = relq[(p >> 17)      * 16];
            accP = __hfma2(u2h(a.x), u2h(b.x), accP);
            accQ = __hfma2(u2h(a.y), u2h(b.y), accQ);
        }
        float2 u = __half22float2(accP);
        float2 v = __half22float2(accQ);
        f0 += u.x; f1 += u.y; f2 += v.x; f3 += v.y;
    }

    // ultra-rare tail (deg > 32): sub==0 half only (avoid double count)
    for (int t = 32; t < deg; t++) {
        unsigned p = g_edges[ebase + t];
        if (sub == 0) {
            uint2 a = entq[(p & 0x1FFFFu) * 16];
            uint2 b = relq[(p >> 17)      * 16];
            float2 pa = __half22float2(u2h(a.x));
            float2 pb = __half22float2(u2h(b.x));
            float2 pc = __half22float2(u2h(a.y));
            float2 pd = __half22float2(u2h(b.y));
            f0 += pa.x * pb.x; f1 += pa.y * pb.y;
            f2 += pc.x * pd.x; f3 += pc.y * pd.y;
        }
    }

    // combine the two half-warps (same dims, disjoint edge subsets)
    f0 += __shfl_xor_sync(0xFFFFFFFFu, f0, 16);
    f1 += __shfl_xor_sync(0xFFFFFFFFu, f1, 16);
    f2 += __shfl_xor_sync(0xFFFFFFFFu, f2, 16);
    f3 += __shfl_xor_sync(0xFFFFFFFFu, f3, 16);

    float ss = f0 * f0 + f1 * f1 + f2 * f2 + f3 * f3;
    #pragma unroll
    for (int o = 8; o > 0; o >>= 1)
        ss += __shfl_xor_sync(0xFFFFFFFFu, ss, o);

    float inv = 1.0f / fmaxf(sqrtf(ss), 1e-12f);
    f0 *= inv; f1 *= inv; f2 *= inv; f3 *= inv;

    if (sub == 0) {
        long long idx = (long long)row * 16 + q;
        if (!final_hop) {
            uint2 o;
            o.x = h2u(__floats2half2_rn(f0, f1));
            o.y = h2u(__floats2half2_rn(f2, f3));
            reinterpret_cast<uint2*>(dst)[idx] = o;
        } else {
            uint2 ha = reinterpret_cast<const uint2*>(g_entA)[idx];
            uint2 hb = reinterpret_cast<const uint2*>(g_entB)[idx];
            float2 a0 = __half22float2(u2h(ha.x));
            float2 a1 = __half22float2(u2h(ha.y));
            float2 b0 = __half22float2(u2h(hb.x));
            float2 b1 = __half22float2(u2h(hb.y));
            float sx = a0.x + b0.x + f0;
            float sy = a0.y + b0.y + f1;
            float sz = a1.x + b1.x + f2;
            float sw = a1.y + b1.y + f3;

            float4 e0 = base_ent[idx];
            out_ent[idx] = make_float4(e0.x + sx, e0.y + sy,
                                       e0.z + sz, e0.w + sw);
            if (row < N_DRUG) {
                float4 d0 = base_drug[idx];
                out_drug[idx] = make_float4(d0.x + sx, d0.y + sy,
                                            d0.z + sz, d0.w + sw);
            }
        }
    }
}

// ---------------------------------------------------------------------------
extern "C" void kernel_launch(void* const* d_in, const int* in_sizes, int n_in,
                              void* d_out, int out_size) {
    const float* ent0  = (const float*)d_in[0];
    const float* drug0 = (const float*)d_in[1];
    const float* rel0  = (const float*)d_in[2];
    const int*   eidx  = (const int*)d_in[3];
    const int*   etype = (const int*)d_in[4];

    float* out      = (float*)d_out;
    float* out_ent  = out;
    float* out_drug = out + (size_t)N_ENT * DIM;
    float* out_rel  = out + (size_t)(N_ENT + N_DRUG) * DIM;

    void *p0, *pA, *pB, *pR0, *pRN, *pC;
    cudaGetSymbolAddress(&p0,  g_ent0h);
    cudaGetSymbolAddress(&pA,  g_entA);
    cudaGetSymbolAddress(&pB,  g_entB);
    cudaGetSymbolAddress(&pR0, g_rel0z);
    cudaGetSymbolAddress(&pRN, g_relnz);
    cudaGetSymbolAddress(&pC,  g_cnt);

    // CSR-bucket build + fp16 conversions + relation tables
    cudaMemsetAsync(pC, 0, N_ENT * sizeof(int), 0);
    fill_kernel<<<(N_EDGE / 8 + 255) / 256, 256>>>(eidx, etype);
    conv_kernel<<<(N_ENT * 32 + 255) / 256, 256>>>((const float2*)ent0);
    rel_kernel<<<N_REL, 32>>>(rel0, out_rel);

    const int blocks = (N_ENT * 32 + 255) / 256;

    // hop 0: fp16(ent0) * rel0 -> entA
    gather_kernel<<<blocks, 256>>>(
        (const __half2*)p0, (const __half2*)pR0, (__half2*)pA,
        nullptr, nullptr, nullptr, nullptr, 0);
    // hop 1: entA * norm(rel) -> entB
    gather_kernel<<<blocks, 256>>>(
        (const __half2*)pA, (const __half2*)pRN, (__half2*)pB,
        nullptr, nullptr, nullptr, nullptr, 0);
    // hop 2 (final): entB * norm(rel) -> n3; out = base + entA + entB + n3
    gather_kernel<<<blocks, 256>>>(
        (const __half2*)pB, (const __half2*)pRN, nullptr,
        (const float4*)ent0, (const float4*)drug0,
        (float4*)out_ent, (float4*)out_drug, 1);
}

// round 12
// speedup vs baseline: 1.1269x; 1.1269x over previous
#include <cuda_runtime.h>
#include <cuda_fp16.h>
#include <cstdint>

#define N_ENT   100000
#define N_DRUG  2000
#define N_REL   51
#define N_EDGE  1000000
#define DIM     64
#define BUCKET  64          // per-head capacity; Poisson(10) max over 100K ~35

// fp16 tables (row = 64 halves = 128B = one cache line).
// Rel tables have a leading ZERO row (row 0 never written): pad edge slots
// are packed-0 -> gather ent[0] (valid row) * rel[0] (zeros) -> contribute 0.
__device__ __half2  g_ent0h[N_ENT * 32];
__device__ __half2  g_entA [N_ENT * 32];
__device__ __half2  g_entB [N_ENT * 32];
__device__ __half2  g_rel0z[(N_REL + 1) * 32];   // fp16 rel0, shifted +1
__device__ __half2  g_relnz[(N_REL + 1) * 32];   // fp16 norm(rel0), shifted +1
__device__ int      g_cnt  [N_ENT];
__device__ unsigned g_edges[N_ENT * BUCKET];     // packed: tail | (rel+1)<<17

// ---------------------------------------------------------------------------
// Fused: fp32->fp16 conversion of ent0 (all 1.6M threads, streaming) +
// bucket fill (first 125K threads, 8 edges each, 8 ATOMGs in flight).
// The streaming conv traffic hides the fill's atomic latency.
// ---------------------------------------------------------------------------
__global__ void prep_kernel(const float4* __restrict__ ent0,
                            const int*    __restrict__ eidx,
                            const int*    __restrict__ etype) {
    int i = blockIdx.x * blockDim.x + threadIdx.x;

    // conv: thread i handles dims [4i, 4i+4) of the flattened table
    if (i < N_ENT * 16) {
        float4 v = ent0[i];
        uint2 o;
        __half2 h0 = __floats2half2_rn(v.x, v.y);
        __half2 h1 = __floats2half2_rn(v.z, v.w);
        o.x = *reinterpret_cast<unsigned*>(&h0);
        o.y = *reinterpret_cast<unsigned*>(&h1);
        reinterpret_cast<uint2*>(g_ent0h)[i] = o;
    }

    // fill: first N_EDGE/8 threads scatter 8 edges each
    if (i < N_EDGE / 8) {
        int base = i * 8;
        #pragma unroll
        for (int k = 0; k < 8; k++) {
            int e  = base + k;
            int h  = eidx[e];
            int tl = eidx[N_EDGE + e];
            int r  = etype[e];
            int pos = atomicAdd(&g_cnt[h], 1);
            if (pos < BUCKET)
                g_edges[(long long)h * BUCKET + pos] =
                    (unsigned)tl | ((unsigned)(r + 1) << 17);
        }
    }
}

// ---------------------------------------------------------------------------
// Relations (once): out_rel = rel0 + 3*normalize(rel0) (norm is idempotent);
// fp16 shifted tables rows 1..N_REL (row 0 stays all-zero).
// ---------------------------------------------------------------------------
__global__ void rel_kernel(const float* __restrict__ rel0,
                           float* __restrict__ out_rel) {
    int row  = blockIdx.x;
    int lane = threadIdx.x;

    float2 v = reinterpret_cast<const float2*>(rel0)[row * 32 + lane];
    float ss = v.x * v.x + v.y * v.y;
    #pragma unroll
    for (int o = 16; o > 0; o >>= 1)
        ss += __shfl_xor_sync(0xFFFFFFFFu, ss, o);

    float inv = 1.0f / fmaxf(sqrtf(ss), 1e-12f);
    float2 n = { v.x * inv, v.y * inv };

    g_rel0z[(row + 1) * 32 + lane] = __float22half2_rn(v);
    g_relnz[(row + 1) * 32 + lane] = __float22half2_rn(n);

    float2 o2 = { v.x + 3.0f * n.x, v.y + 3.0f * n.y };
    reinterpret_cast<float2*>(out_rel)[row * 32 + lane] = o2;
}

// ---------------------------------------------------------------------------
// Fused gather + L2-normalize, fp16 tables. One warp per row, half2 per lane
// (row = 128B = one cache line). Unmasked chunk-4 loop; DEFERRED FLUSH: each
// chunk's half2 partial is hadd2'd into a running half2 accumulator,
// converted to fp32 once after the loop (saves ~1 instr/edge vs per-chunk
// flush). Pad slots (packed 0) hit the rel zero-row -> contribute 0.
//   final_hop=0: dst[row] = fp16(n)
//   final_hop=1: out_ent = base + entA + entB + n ; ditto drug rows
// ---------------------------------------------------------------------------
__global__ void __launch_bounds__(256)
gather_kernel(const __half2* __restrict__ ent,
              const __half2* __restrict__ rel,
              __half2*       __restrict__ dst,
              const float2*  __restrict__ base_ent,
              const float2*  __restrict__ base_drug,
              float2*        __restrict__ out_ent,
              float2*        __restrict__ out_drug,
              int final_hop) {
    int row  = (blockIdx.x * blockDim.x + threadIdx.x) >> 5;
    int lane = threadIdx.x & 31;
    if (row >= N_ENT) return;

    int deg = g_cnt[row];
    if (deg > BUCKET) deg = BUCKET;
    long long ebase = (long long)row * BUCKET;
    unsigned myp = g_edges[ebase + lane];    // coalesced: row's first 32 edges

    const __half2* entL = ent + lane;
    const __half2* relL = rel + lane;

    int dmain = deg < 32 ? deg : 32;
    int slots = (dmain + 3) & ~3;
    if (slots == 0) slots = 4;               // deg==0 rows: one all-pad chunk

    __half2 hs = __float2half2_rn(0.f);      // deferred fp16 accumulator
    for (int i = 0; i < slots; i += 4) {
        unsigned p0 = __shfl_sync(0xFFFFFFFFu, myp, i);
        unsigned p1 = __shfl_sync(0xFFFFFFFFu, myp, i + 1);
        unsigned p2 = __shfl_sync(0xFFFFFFFFu, myp, i + 2);
        unsigned p3 = __shfl_sync(0xFFFFFFFFu, myp, i + 3);
        __half2 a0 = entL[(p0 & 0x1FFFFu) * 32];
        __half2 b0 = relL[(p0 >> 17)      * 32];
        __half2 a1 = entL[(p1 & 0x1FFFFu) * 32];
        __half2 b1 = relL[(p1 >> 17)      * 32];
        __half2 a2 = entL[(p2 & 0x1FFFFu) * 32];
        __half2 b2 = relL[(p2 >> 17)      * 32];
        __half2 a3 = entL[(p3 & 0x1FFFFu) * 32];
        __half2 b3 = relL[(p3 >> 17)      * 32];
        __half2 h0 = __hmul2(a0, b0);
        __half2 h1 = __hmul2(a1, b1);
        h0 = __hfma2(a2, b2, h0);
        h1 = __hfma2(a3, b3, h1);
        hs = __hadd2(hs, __hadd2(h0, h1));
    }
    float2 f = __half22float2(hs);
    float fx = f.x, fy = f.y;

    // ultra-rare tail (deg > 32), fp32 path
    for (int t = 32; t < deg; t++) {
        unsigned p = g_edges[ebase + t];
        float2 a = __half22float2(entL[(p & 0x1FFFFu) * 32]);
        float2 b = __half22float2(relL[(p >> 17)      * 32]);
        fx += a.x * b.x;
        fy += a.y * b.y;
    }

    float ss = fx * fx + fy * fy;
    #pragma unroll
    for (int o = 16; o > 0; o >>= 1)
        ss += __shfl_xor_sync(0xFFFFFFFFu, ss, o);

    float inv = rsqrtf(fmaxf(ss, 1e-24f));   // == 1/max(sqrt(ss),1e-12)
    float2 n = make_float2(fx * inv, fy * inv);

    long long idx = (long long)row * 32 + lane;

    if (!final_hop) {
        dst[idx] = __float22half2_rn(n);
    } else {
        float2 a1v = __half22float2(g_entA[idx]);
        float2 a2v = __half22float2(g_entB[idx]);
        float sx = a1v.x + a2v.x + n.x;
        float sy = a1v.y + a2v.y + n.y;

        float2 e0 = base_ent[idx];
        out_ent[idx] = make_float2(e0.x + sx, e0.y + sy);
        if (row < N_DRUG) {
            float2 d0 = base_drug[idx];
            out_drug[idx] = make_float2(d0.x + sx, d0.y + sy);
        }
    }
}

// ---------------------------------------------------------------------------
extern "C" void kernel_launch(void* const* d_in, const int* in_sizes, int n_in,
                              void* d_out, int out_size) {
    const float* ent0  = (const float*)d_in[0];
    const float* drug0 = (const float*)d_in[1];
    const float* rel0  = (const float*)d_in[2];
    const int*   eidx  = (const int*)d_in[3];
    const int*   etype = (const int*)d_in[4];

    float* out      = (float*)d_out;
    float* out_ent  = out;
    float* out_drug = out + (size_t)N_ENT * DIM;
    float* out_rel  = out + (size_t)(N_ENT + N_DRUG) * DIM;

    void *p0, *pA, *pB, *pR0, *pRN, *pC;
    cudaGetSymbolAddress(&p0,  g_ent0h);
    cudaGetSymbolAddress(&pA,  g_entA);
    cudaGetSymbolAddress(&pB,  g_entB);
    cudaGetSymbolAddress(&pR0, g_rel0z);
    cudaGetSymbolAddress(&pRN, g_relnz);
    cudaGetSymbolAddress(&pC,  g_cnt);

    // counters reset + fused conv/fill + relation tables
    cudaMemsetAsync(pC, 0, N_ENT * sizeof(int), 0);
    prep_kernel<<<(N_ENT * 16 + 255) / 256, 256>>>(
        (const float4*)ent0, eidx, etype);
    rel_kernel<<<N_REL, 32>>>(rel0, out_rel);

    const int blocks = (N_ENT * 32 + 255) / 256;

    // hop 0: fp16(ent0) * rel0 -> entA
    gather_kernel<<<blocks, 256>>>(
        (const __half2*)p0, (const __half2*)pR0, (__half2*)pA,
        nullptr, nullptr, nullptr, nullptr, 0);
    // hop 1: entA * norm(rel) -> entB
    gather_kernel<<<blocks, 256>>>(
        (const __half2*)pA, (const __half2*)pRN, (__half2*)pB,
        nullptr, nullptr, nullptr, nullptr, 0);
    // hop 2 (final): entB * norm(rel) -> n3; out = base + entA + entB + n3
    gather_kernel<<<blocks, 256>>>(
        (const __half2*)pB, (const __half2*)pRN, nullptr,
        (const float2*)ent0, (const float2*)drug0,
        (float2*)out_ent, (float2*)out_drug, 1);
}

// round 13
// speedup vs baseline: 1.3767x; 1.2216x over previous
#include <cuda_runtime.h>
#include <cuda_fp16.h>
#include <cstdint>

#define N_ENT   100000
#define N_DRUG  2000
#define N_REL   51
#define N_EDGE  1000000
#define DIM     64
#define BUCKET  64          // per-head capacity; Poisson(10) max over 100K ~35

// fp16 tables (row = 64 halves = 128B = one cache line).
// Rel tables have a leading ZERO row (row 0 never written): pad edge slots
// are packed-0 -> gather ent[0] (valid row) * rel[0] (zeros) -> contribute 0.
__device__ __half2  g_ent0h[N_ENT * 32];
__device__ __half2  g_entA [N_ENT * 32];
__device__ __half2  g_entB [N_ENT * 32];
__device__ __half2  g_rel0z[(N_REL + 1) * 32];   // fp16 rel0, shifted +1
__device__ __half2  g_relnz[(N_REL + 1) * 32];   // fp16 norm(rel0), shifted +1
__device__ int      g_cnt  [N_ENT];
__device__ unsigned g_edges[N_ENT * BUCKET];     // packed: tail | (rel+1)<<17

static __device__ __forceinline__ __half2 u2h(unsigned u) {
    return *reinterpret_cast<__half2*>(&u);
}

// ---------------------------------------------------------------------------
// Fused: fp32->fp16 conversion of ent0 (all 1.6M threads, streaming) +
// bucket fill (first 125K threads, 8 edges each, 8 ATOMGs in flight).
// ---------------------------------------------------------------------------
__global__ void prep_kernel(const float4* __restrict__ ent0,
                            const int*    __restrict__ eidx,
                            const int*    __restrict__ etype) {
    int i = blockIdx.x * blockDim.x + threadIdx.x;

    if (i < N_ENT * 16) {
        float4 v = ent0[i];
        uint2 o;
        __half2 h0 = __floats2half2_rn(v.x, v.y);
        __half2 h1 = __floats2half2_rn(v.z, v.w);
        o.x = *reinterpret_cast<unsigned*>(&h0);
        o.y = *reinterpret_cast<unsigned*>(&h1);
        reinterpret_cast<uint2*>(g_ent0h)[i] = o;
    }

    if (i < N_EDGE / 8) {
        int base = i * 8;
        #pragma unroll
        for (int k = 0; k < 8; k++) {
            int e  = base + k;
            int h  = eidx[e];
            int tl = eidx[N_EDGE + e];
            int r  = etype[e];
            int pos = atomicAdd(&g_cnt[h], 1);
            if (pos < BUCKET)
                g_edges[(long long)h * BUCKET + pos] =
                    (unsigned)tl | ((unsigned)(r + 1) << 17);
        }
    }
}

// ---------------------------------------------------------------------------
// Relations (once): out_rel = rel0 + 3*normalize(rel0) (norm is idempotent);
// fp16 shifted tables rows 1..N_REL (row 0 stays all-zero).
// ---------------------------------------------------------------------------
__global__ void rel_kernel(const float* __restrict__ rel0,
                           float* __restrict__ out_rel) {
    int row  = blockIdx.x;
    int lane = threadIdx.x;

    float2 v = reinterpret_cast<const float2*>(rel0)[row * 32 + lane];
    float ss = v.x * v.x + v.y * v.y;
    #pragma unroll
    for (int o = 16; o > 0; o >>= 1)
        ss += __shfl_xor_sync(0xFFFFFFFFu, ss, o);

    float inv = 1.0f / fmaxf(sqrtf(ss), 1e-12f);
    float2 n = { v.x * inv, v.y * inv };

    g_rel0z[(row + 1) * 32 + lane] = __float22half2_rn(v);
    g_relnz[(row + 1) * 32 + lane] = __float22half2_rn(n);

    float2 o2 = { v.x + 3.0f * n.x, v.y + 3.0f * n.y };
    reinterpret_cast<float2*>(out_rel)[row * 32 + lane] = o2;
}

// ---------------------------------------------------------------------------
// Fused gather + L2-normalize, fp16 tables. TWO ROWS PER WARP: lanes 0-15
// own row 2w, lanes 16-31 own row 2w+1. Each lane covers 4 dims via uint2
// (LDG.64); 16 lanes * 8B = full 128B row. Edge words held as uint2 per lane
// (32 slots per row); one shfl per edge-pair serves both halves. Uniform loop
// bound = max(chunksA, chunksB); the shorter row processes pad slots that hit
// the rel zero-row -> contribute 0 (no masking, no divergence).
//   final_hop=0: dst[row] = fp16(n)
//   final_hop=1: out_ent = base + entA + entB + n ; ditto drug rows
// ---------------------------------------------------------------------------
__global__ void __launch_bounds__(256)
gather_kernel(const uint2*  __restrict__ ent,   // fp16 table, uint2 = 4 halves
              const uint2*  __restrict__ rel,
              uint2*        __restrict__ dst,
              const float4* __restrict__ base_ent,
              const float4* __restrict__ base_drug,
              float4*       __restrict__ out_ent,
              float4*       __restrict__ out_drug,
              int final_hop) {
    int gw   = (blockIdx.x * blockDim.x + threadIdx.x) >> 5;
    int lane = threadIdx.x & 31;
    int sub  = lane >> 4;       // which row of the pair this half-warp owns
    int q    = lane & 15;       // uint2 index within the row (dims 4q..4q+3)
    int row  = gw * 2 + sub;
    if (row >= N_ENT) return;   // N_ENT even -> whole warp exits together

    int deg = g_cnt[row];
    if (deg > BUCKET) deg = BUCKET;

    // row's 32 edge slots as 16 uint2 across the half-warp (slots 2q, 2q+1)
    uint2 myq = reinterpret_cast<const uint2*>(g_edges)[row * 32 + q];

    int myChunks = ((deg < 32 ? deg : 32) + 3) >> 2;
    int chunks = max(myChunks, __shfl_xor_sync(0xFFFFFFFFu, myChunks, 16));

    const uint2* entq = ent + q;
    const uint2* relq = rel + q;
    int subbase = sub << 4;

    float f0 = 0.f, f1 = 0.f, f2 = 0.f, f3 = 0.f;

    for (int c = 0; c < chunks; c++) {
        int s = c * 2 + subbase;        // source lane within own half
        unsigned p0 = __shfl_sync(0xFFFFFFFFu, myq.x, s);
        unsigned p1 = __shfl_sync(0xFFFFFFFFu, myq.y, s);
        unsigned p2 = __shfl_sync(0xFFFFFFFFu, myq.x, s + 1);
        unsigned p3 = __shfl_sync(0xFFFFFFFFu, myq.y, s + 1);

        uint2 a0 = entq[(p0 & 0x1FFFFu) * 16];
        uint2 b0 = relq[(p0 >> 17)      * 16];
        uint2 a1 = entq[(p1 & 0x1FFFFu) * 16];
        uint2 b1 = relq[(p1 >> 17)      * 16];
        uint2 a2 = entq[(p2 & 0x1FFFFu) * 16];
        uint2 b2 = relq[(p2 >> 17)      * 16];
        uint2 a3 = entq[(p3 & 0x1FFFFu) * 16];
        uint2 b3 = relq[(p3 >> 17)      * 16];

        __half2 accP = __hmul2(u2h(a0.x), u2h(b0.x));
        __half2 accQ = __hmul2(u2h(a0.y), u2h(b0.y));
        accP = __hfma2(u2h(a1.x), u2h(b1.x), accP);
        accQ = __hfma2(u2h(a1.y), u2h(b1.y), accQ);
        accP = __hfma2(u2h(a2.x), u2h(b2.x), accP);
        accQ = __hfma2(u2h(a2.y), u2h(b2.y), accQ);
        accP = __hfma2(u2h(a3.x), u2h(b3.x), accP);
        accQ = __hfma2(u2h(a3.y), u2h(b3.y), accQ);

        float2 u = __half22float2(accP);
        float2 v = __half22float2(accQ);
        f0 += u.x; f1 += u.y; f2 += v.x; f3 += v.y;
    }

    // ultra-rare tail (deg > 32), fp32 path, per-half
    for (int t = 32; t < deg; t++) {
        unsigned p = g_edges[(long long)row * BUCKET + t];
        uint2 a = entq[(p & 0x1FFFFu) * 16];
        uint2 b = relq[(p >> 17)      * 16];
        float2 pa = __half22float2(u2h(a.x));
        float2 pb = __half22float2(u2h(b.x));
        float2 pc = __half22float2(u2h(a.y));
        float2 pd = __half22float2(u2h(b.y));
        f0 += pa.x * pb.x; f1 += pa.y * pb.y;
        f2 += pc.x * pd.x; f3 += pc.y * pd.y;
    }

    // reduce within the 16-lane half (xor offsets 1..8 stay inside the half)
    float ss = f0 * f0 + f1 * f1 + f2 * f2 + f3 * f3;
    #pragma unroll
    for (int o = 8; o > 0; o >>= 1)
        ss += __shfl_xor_sync(0xFFFFFFFFu, ss, o);

    float inv = rsqrtf(fmaxf(ss, 1e-24f));   // == 1/max(sqrt(ss),1e-12)
    f0 *= inv; f1 *= inv; f2 *= inv; f3 *= inv;

    long long idx = (long long)row * 16 + q;

    if (!final_hop) {
        uint2 o;
        __half2 h0 = __floats2half2_rn(f0, f1);
        __half2 h1 = __floats2half2_rn(f2, f3);
        o.x = *reinterpret_cast<unsigned*>(&h0);
        o.y = *reinterpret_cast<unsigned*>(&h1);
        dst[idx] = o;
    } else {
        uint2 ha = reinterpret_cast<const uint2*>(g_entA)[idx];
        uint2 hb = reinterpret_cast<const uint2*>(g_entB)[idx];
        float2 a0 = __half22float2(u2h(ha.x));
        float2 a1 = __half22float2(u2h(ha.y));
        float2 b0 = __half22float2(u2h(hb.x));
        float2 b1 = __half22float2(u2h(hb.y));
        float sx = a0.x + b0.x + f0;
        float sy = a0.y + b0.y + f1;
        float sz = a1.x + b1.x + f2;
        float sw = a1.y + b1.y + f3;

        float4 e0 = base_ent[idx];
        out_ent[idx] = make_float4(e0.x + sx, e0.y + sy,
                                   e0.z + sz, e0.w + sw);
        if (row < N_DRUG) {
            float4 d0 = base_drug[idx];
            out_drug[idx] = make_float4(d0.x + sx, d0.y + sy,
                                        d0.z + sz, d0.w + sw);
        }
    }
}

// ---------------------------------------------------------------------------
extern "C" void kernel_launch(void* const* d_in, const int* in_sizes, int n_in,
                              void* d_out, int out_size) {
    const float* ent0  = (const float*)d_in[0];
    const float* drug0 = (const float*)d_in[1];
    const float* rel0  = (const float*)d_in[2];
    const int*   eidx  = (const int*)d_in[3];
    const int*   etype = (const int*)d_in[4];

    float* out      = (float*)d_out;
    float* out_ent  = out;
    float* out_drug = out + (size_t)N_ENT * DIM;
    float* out_rel  = out + (size_t)(N_ENT + N_DRUG) * DIM;

    void *p0, *pA, *pB, *pR0, *pRN, *pC;
    cudaGetSymbolAddress(&p0,  g_ent0h);
    cudaGetSymbolAddress(&pA,  g_entA);
    cudaGetSymbolAddress(&pB,  g_entB);
    cudaGetSymbolAddress(&pR0, g_rel0z);
    cudaGetSymbolAddress(&pRN, g_relnz);
    cudaGetSymbolAddress(&pC,  g_cnt);

    // counters reset + fused conv/fill + relation tables
    cudaMemsetAsync(pC, 0, N_ENT * sizeof(int), 0);
    prep_kernel<<<(N_ENT * 16 + 255) / 256, 256>>>(
        (const float4*)ent0, eidx, etype);
    rel_kernel<<<N_REL, 32>>>(rel0, out_rel);

    // 2 rows per warp -> N_ENT/2 warps
    const int warps  = N_ENT / 2;
    const int blocks = (warps * 32 + 255) / 256;

    // hop 0: fp16(ent0) * rel0 -> entA
    gather_kernel<<<blocks, 256>>>(
        (const uint2*)p0, (const uint2*)pR0, (uint2*)pA,
        nullptr, nullptr, nullptr, nullptr, 0);
    // hop 1: entA * norm(rel) -> entB
    gather_kernel<<<blocks, 256>>>(
        (const uint2*)pA, (const uint2*)pRN, (uint2*)pB,
        nullptr, nullptr, nullptr, nullptr, 0);
    // hop 2 (final): entB * norm(rel) -> n3; out = base + entA + entB + n3
    gather_kernel<<<blocks, 256>>>(
        (const uint2*)pB, (const uint2*)pRN, nullptr,
        (const float4*)ent0, (const float4*)drug0,
        (float4*)out_ent, (float4*)out_drug, 1);
}